// round 15
// baseline (speedup 1.0000x reference)
#include <cuda_runtime.h>
#include <cuda_fp16.h>
#include <cstdint>

#define NN 100000
#define EE 600000
#define HH 128
#define GG 1000
#define BN_EPS 1e-5f
#define NB_SCAN 98   // ceil(NN/1024)

// ---- scratch (alloc-free: __device__ globals) ----
__device__ __half g_t[NN * HH];    // h + agg (pre-MLP input), fp16
__device__ __half g_h[NN * HH];    // layer output features, fp16
__device__ float g_t3[NN * 3];     // layer-0 pre-MLP (3 feats)
__device__ uint32_t g_wp[9][64 * 128];  // pre-packed fp16 k-pair weights
// CSR scratch
__device__ int g_deg[NN];
__device__ int g_rowptr[NN + 1];
__device__ int g_cursor[NN];
__device__ int g_bsum[128];
__device__ int g_csr[EE];

// smem: Us (fp16 A/activations) + Wp (packed weights, single buffer)
#define US_HSTRIDE 136                    // halves; conflict-free
#define US_BYTES (128 * US_HSTRIDE * 2)   // 34816
#define WP_WSTRIDE 132                    // words; conflict-free
#define WP_BYTES (64 * WP_WSTRIDE * 4)    // 33792
#define SMEM_BYTES (US_BYTES + WP_BYTES)  // 68608 -> 3 CTA/SM

__device__ __forceinline__ void cp_async16(uint32_t saddr, const void* gaddr, int szfill) {
    asm volatile("cp.async.ca.shared.global [%0], [%1], 16, %2;"
                 :: "r"(saddr), "l"(gaddr), "r"(szfill) : "memory");
}
__device__ __forceinline__ void cp_commit() {
    asm volatile("cp.async.commit_group;" ::: "memory");
}
template <int N>
__device__ __forceinline__ void cp_wait() {
    asm volatile("cp.async.wait_group %0;" :: "n"(N) : "memory");
}

// ================= weight pre-pack (+ deg zero) =================
__global__ void k_pack(const float* __restrict__ W2_0, const float* __restrict__ W1s,
                       const float* __restrict__ W2s) {
    int idx = blockIdx.x * 256 + threadIdx.x;
    if (idx < NN) g_deg[idx] = 0;
    if (idx >= 9 * 8192) return;
    int m = idx >> 13;
    int w = idx & 8191;
    int kp = w >> 7;
    int col = w & 127;
    const float* W = (m == 0) ? W2_0 : (m <= 4 ? W1s + (m - 1) * 16384 : W2s + (m - 5) * 16384);
    __half2 h = __floats2half2_rn(W[(2 * kp) * 128 + col], W[(2 * kp + 1) * 128 + col]);
    g_wp[m][w] = *(uint32_t*)&h;
}

// ================= CSR build =================
__global__ void k_hist(const int* __restrict__ ei) {
    int e = blockIdx.x * blockDim.x + threadIdx.x;
    if (e < EE) atomicAdd(&g_deg[ei[EE + e]], 1);
}

__global__ __launch_bounds__(1024) void k_scan1() {
    __shared__ int s[1024];
    int tid = threadIdx.x;
    int i = blockIdx.x * 1024 + tid;
    int v = (i < NN) ? g_deg[i] : 0;
    s[tid] = v;
    __syncthreads();
#pragma unroll
    for (int off = 1; off < 1024; off <<= 1) {
        int t = (tid >= off) ? s[tid - off] : 0;
        __syncthreads();
        s[tid] += t;
        __syncthreads();
    }
    if (i < NN) g_rowptr[i] = s[tid] - v;
    if (tid == 1023) g_bsum[blockIdx.x] = s[1023];
}

// merged scan2+scan3: every block redundantly scans the 98 block sums
__global__ void k_scan3() {
    __shared__ int s[128];
    int tid = threadIdx.x;
    if (tid < 128) s[tid] = (tid < NB_SCAN) ? g_bsum[tid] : 0;
    __syncthreads();
#pragma unroll
    for (int off = 1; off < 128; off <<= 1) {
        int t = (tid < 128 && tid >= off) ? s[tid - off] : 0;
        __syncthreads();
        if (tid < 128) s[tid] += t;
        __syncthreads();
    }
    int i = blockIdx.x * blockDim.x + tid;
    if (i < NN) {
        int b = i >> 10;
        int add = (b == 0) ? 0 : s[b - 1];   // exclusive prefix of block sums
        int r = g_rowptr[i] + add;
        g_rowptr[i] = r;
        g_cursor[i] = r;
    }
    if (i == 0) g_rowptr[NN] = EE;
}

__global__ void k_reorder(const int* __restrict__ ei) {
    int e = blockIdx.x * blockDim.x + threadIdx.x;
    if (e >= EE) return;
    int s = ei[e];
    int d = ei[EE + e];
    int pos = atomicAdd(&g_cursor[d], 1);
    g_csr[pos] = s;
}

// ================= gathers =================
__global__ void k_gather3(const float* __restrict__ x, const float* __restrict__ bc,
                          float* __restrict__ out) {
    int n = blockIdx.x * blockDim.x + threadIdx.x;
    if (n < GG) out[n] = bc[0];
    if (n >= NN) return;
    int beg = g_rowptr[n], end = g_rowptr[n + 1];
    float a0 = x[n * 3 + 0], a1 = x[n * 3 + 1], a2 = x[n * 3 + 2];
    for (int p = beg; p < end; p++) {
        int s = g_csr[p];
        a0 += x[s * 3 + 0];
        a1 += x[s * 3 + 1];
        a2 += x[s * 3 + 2];
    }
    g_t3[n * 3 + 0] = a0;
    g_t3[n * 3 + 1] = a1;
    g_t3[n * 3 + 2] = a2;
}

__device__ __forceinline__ void acc_half4(float4& acc, uint2 r) {
    float2 f0 = __half22float2(*(__half2*)&r.x);
    float2 f1 = __half22float2(*(__half2*)&r.y);
    acc.x += f0.x;
    acc.y += f0.y;
    acc.z += f1.x;
    acc.w += f1.y;
}

__global__ __launch_bounds__(256) void k_gather() {
    int n = blockIdx.x * 8 + (threadIdx.x >> 5);
    if (n >= NN) return;
    int lane = threadIdx.x & 31;
    int beg = g_rowptr[n], end = g_rowptr[n + 1];
    float4 acc = make_float4(0.f, 0.f, 0.f, 0.f);
    acc_half4(acc, *((const uint2*)&g_h[n * HH + lane * 4]));
    int p = beg;
    for (; p + 3 < end; p += 4) {
        int s0 = g_csr[p], s1 = g_csr[p + 1], s2 = g_csr[p + 2], s3 = g_csr[p + 3];
        uint2 v0 = *((const uint2*)&g_h[s0 * HH + lane * 4]);
        uint2 v1 = *((const uint2*)&g_h[s1 * HH + lane * 4]);
        uint2 v2 = *((const uint2*)&g_h[s2 * HH + lane * 4]);
        uint2 v3 = *((const uint2*)&g_h[s3 * HH + lane * 4]);
        acc_half4(acc, v0);
        acc_half4(acc, v1);
        acc_half4(acc, v2);
        acc_half4(acc, v3);
    }
    for (; p < end; p++) acc_half4(acc, *((const uint2*)&g_h[g_csr[p] * HH + lane * 4]));
    __half2 o0 = __floats2half2_rn(acc.x, acc.y);
    __half2 o1 = __floats2half2_rn(acc.z, acc.w);
    uint2 o;
    o.x = *(uint32_t*)&o0;
    o.y = *(uint32_t*)&o1;
    *((uint2*)&g_t[n * HH + lane * 4]) = o;
}

// ================= helpers for k_fused =================
__device__ __forceinline__ void stage_weights_async(uint32_t wp_s, const uint32_t* __restrict__ src, int tid) {
#pragma unroll
    for (int i = 0; i < 8; i++) {
        int idx = tid + i * 256;      // uint4 idx 0..2047
        int kp = idx >> 5;
        int c4 = (idx & 31) * 4;
        cp_async16(wp_s + (kp * WP_WSTRIDE + c4) * 4, &src[kp * 128 + c4], 16);
    }
}

__device__ __forceinline__ void ldsm_a(uint32_t a[4], const __half* Us, int rb, int k0, int lane) {
    const __half* p = &Us[(rb + (lane & 15)) * US_HSTRIDE + k0 + ((lane >> 4) << 3)];
    uint32_t addr = (uint32_t)__cvta_generic_to_shared(p);
    asm volatile("ldmatrix.sync.aligned.m8n8.x4.shared.b16 {%0,%1,%2,%3}, [%4];"
                 : "=r"(a[0]), "=r"(a[1]), "=r"(a[2]), "=r"(a[3]) : "r"(addr));
}

// one 64-col N-pass of full-K (128) fp16 MMA: c[2][4][4] covers 32 rows x 32 cols
__device__ __forceinline__ void mma_pass(
    float c[2][4][4], const __half* Us, const uint32_t* Wp,
    int wm, int colbase, int gq, int tg, int lane) {
#pragma unroll
    for (int ks = 0; ks < 8; ks++) {
        int k0 = ks * 16;
        int kp0 = ks * 8;
        uint32_t a[2][4];
        ldsm_a(a[0], Us, wm * 32, k0, lane);
        ldsm_a(a[1], Us, wm * 32 + 16, k0, lane);
        uint32_t b[4][2];
#pragma unroll
        for (int nt = 0; nt < 4; nt++) {
            int col = colbase + nt * 8 + gq;
            b[nt][0] = Wp[(kp0 + tg) * WP_WSTRIDE + col];
            b[nt][1] = Wp[(kp0 + 4 + tg) * WP_WSTRIDE + col];
        }
#pragma unroll
        for (int mt = 0; mt < 2; mt++)
#pragma unroll
            for (int nt = 0; nt < 4; nt++) {
                asm volatile(
                    "mma.sync.aligned.m16n8k16.row.col.f32.f16.f16.f32 "
                    "{%0,%1,%2,%3}, {%4,%5,%6,%7}, {%8,%9}, {%0,%1,%2,%3};"
                    : "+f"(c[mt][nt][0]), "+f"(c[mt][nt][1]),
                      "+f"(c[mt][nt][2]), "+f"(c[mt][nt][3])
                    : "r"(a[mt][0]), "r"(a[mt][1]), "r"(a[mt][2]), "r"(a[mt][3]),
                      "r"(b[nt][0]), "r"(b[nt][1]));
            }
    }
}

// ================= fused per-layer MLP (2 N-passes, 3 CTA/SM) =================
__global__ __launch_bounds__(256, 3) void k_fused(
    int layer0, int last, int m1, int m2,
    const float* __restrict__ W1_0, const float* __restrict__ b1,
    const float* __restrict__ gam, const float* __restrict__ bet,
    const float* __restrict__ mu, const float* __restrict__ var,
    const float* __restrict__ b2,
    const int* __restrict__ batch, const float* __restrict__ Wc,
    float* __restrict__ out) {
    extern __shared__ char smem[];
    __half* Us = (__half*)smem;
    uint32_t* Wp = (uint32_t*)(smem + US_BYTES);
    float* Xf = (float*)(smem + US_BYTES);   // alias Wp (layer0 params / rowdot)
    uint32_t us_s = (uint32_t)__cvta_generic_to_shared(Us);
    uint32_t wp_s = (uint32_t)__cvta_generic_to_shared(Wp);

    int tid = threadIdx.x;
    int warp = tid >> 5, lane = tid & 31;
    int wm = warp & 3;    // 4 warps over M (32 rows)
    int wn = warp >> 2;   // 2 warps over N within a 64-col pass (32 cols)
    int gq = lane >> 2;
    int tg = lane & 3;
    int row0 = blockIdx.x * 128;

    // ================= stage 1 =================
    if (layer0) {
        float* W1s = Xf;          // 384
        float* sc = Xf + 384;     // 128
        float* sh = Xf + 512;     // 128
        float* t3s = Xf + 640;    // 384
        for (int i = tid; i < 384; i += 256) {
            W1s[i] = W1_0[i];
            int gi = row0 * 3 + i;
            t3s[i] = (gi < NN * 3) ? g_t3[gi] : 0.f;
        }
        if (tid < 128) {
            float s = gam[tid] * rsqrtf(var[tid] + BN_EPS);
            sc[tid] = s;
            sh[tid] = bet[tid] + (b1[tid] - mu[tid]) * s;
        }
        __syncthreads();
#pragma unroll 4
        for (int i = 0; i < 64; i++) {
            int idx = tid + i * 256;
            int r = idx >> 7, c = idx & 127;
            float x0 = t3s[r * 3 + 0];
            float x1 = t3s[r * 3 + 1];
            float x2 = t3s[r * 3 + 2];
            float u = x0 * W1s[c] + x1 * W1s[128 + c] + x2 * W1s[256 + c];
            u = fmaxf(u * sc[c] + sh[c], 0.f);
            Us[r * US_HSTRIDE + c] = __float2half(u);
        }
        __syncthreads();
        // stage W2 into Wp (params fully consumed)
        stage_weights_async(wp_s, g_wp[m2], tid);
        cp_commit();
        cp_wait<0>();
        __syncthreads();
    } else {
        // stage A tile + W1
#pragma unroll
        for (int i = 0; i < 8; i++) {
            int idx = tid + i * 256;   // 2048 x 16B
            int r = idx >> 4;
            int q = idx & 15;
            int row = row0 + r;
            cp_async16(us_s + (r * US_HSTRIDE + q * 8) * 2,
                       &g_t[row * 128 + q * 8], (row < NN) ? 16 : 0);
        }
        stage_weights_async(wp_s, g_wp[m1], tid);
        cp_commit();
        cp_wait<0>();
        __syncthreads();

        float c[2][4][4];
        uint32_t pk0[16];

        // ---- pass 0 (cols [wn*32, wn*32+32)) ----
#pragma unroll
        for (int mt = 0; mt < 2; mt++)
#pragma unroll
            for (int nt = 0; nt < 4; nt++)
#pragma unroll
                for (int r = 0; r < 4; r++) c[mt][nt][r] = 0.f;
        mma_pass(c, Us, Wp, wm, wn * 32, gq, tg, lane);
        // pack BN+ReLU results into registers
#pragma unroll
        for (int nt = 0; nt < 4; nt++) {
            int col = wn * 32 + nt * 8 + tg * 2;
            float s0 = gam[col] * rsqrtf(var[col] + BN_EPS);
            float s1 = gam[col + 1] * rsqrtf(var[col + 1] + BN_EPS);
            float sh0 = bet[col] + (b1[col] - mu[col]) * s0;
            float sh1 = bet[col + 1] + (b1[col + 1] - mu[col + 1]) * s1;
#pragma unroll
            for (int mt = 0; mt < 2; mt++)
#pragma unroll
                for (int half = 0; half < 2; half++) {
                    float v0 = fmaxf(c[mt][nt][half * 2 + 0] * s0 + sh0, 0.f);
                    float v1 = fmaxf(c[mt][nt][half * 2 + 1] * s1 + sh1, 0.f);
                    __half2 h = __floats2half2_rn(v0, v1);
                    pk0[nt * 4 + mt * 2 + half] = *(uint32_t*)&h;
                }
        }

        // ---- pass 1 (cols [64+wn*32, 64+wn*32+32)) ----
#pragma unroll
        for (int mt = 0; mt < 2; mt++)
#pragma unroll
            for (int nt = 0; nt < 4; nt++)
#pragma unroll
                for (int r = 0; r < 4; r++) c[mt][nt][r] = 0.f;
        mma_pass(c, Us, Wp, wm, 64 + wn * 32, gq, tg, lane);

        __syncthreads();   // all Us/Wp reads complete

        // stage W2 (overlaps with epilogue writes below)
        stage_weights_async(wp_s, g_wp[m2], tid);
        cp_commit();

        // write pass-0 packed results
#pragma unroll
        for (int nt = 0; nt < 4; nt++) {
            int col = wn * 32 + nt * 8 + tg * 2;
#pragma unroll
            for (int mt = 0; mt < 2; mt++)
#pragma unroll
                for (int half = 0; half < 2; half++) {
                    int r = wm * 32 + mt * 16 + gq + half * 8;
                    *(uint32_t*)&Us[r * US_HSTRIDE + col] = pk0[nt * 4 + mt * 2 + half];
                }
        }
        // compute + write pass-1 results
#pragma unroll
        for (int nt = 0; nt < 4; nt++) {
            int col = 64 + wn * 32 + nt * 8 + tg * 2;
            float s0 = gam[col] * rsqrtf(var[col] + BN_EPS);
            float s1 = gam[col + 1] * rsqrtf(var[col + 1] + BN_EPS);
            float sh0 = bet[col] + (b1[col] - mu[col]) * s0;
            float sh1 = bet[col + 1] + (b1[col + 1] - mu[col + 1]) * s1;
#pragma unroll
            for (int mt = 0; mt < 2; mt++)
#pragma unroll
                for (int half = 0; half < 2; half++) {
                    int r = wm * 32 + mt * 16 + gq + half * 8;
                    float v0 = fmaxf(c[mt][nt][half * 2 + 0] * s0 + sh0, 0.f);
                    float v1 = fmaxf(c[mt][nt][half * 2 + 1] * s1 + sh1, 0.f);
                    *((__half2*)&Us[r * US_HSTRIDE + col]) = __floats2half2_rn(v0, v1);
                }
        }
        cp_wait<0>();
        __syncthreads();
    }

    // ================= stage 2: h = ReLU(Us @ W2 + b2) =================
    float pacc[4] = {0.f, 0.f, 0.f, 0.f};
#pragma unroll
    for (int pass = 0; pass < 2; pass++) {
        float c[2][4][4];
#pragma unroll
        for (int mt = 0; mt < 2; mt++)
#pragma unroll
            for (int nt = 0; nt < 4; nt++)
#pragma unroll
                for (int r = 0; r < 4; r++) c[mt][nt][r] = 0.f;
        mma_pass(c, Us, Wp, wm, pass * 64 + wn * 32, gq, tg, lane);

        if (!last) {
#pragma unroll
            for (int nt = 0; nt < 4; nt++) {
                int col = pass * 64 + wn * 32 + nt * 8 + tg * 2;
                float sh0 = b2[col];
                float sh1 = b2[col + 1];
#pragma unroll
                for (int mt = 0; mt < 2; mt++)
#pragma unroll
                    for (int half = 0; half < 2; half++) {
                        int row = row0 + wm * 32 + mt * 16 + gq + half * 8;
                        if (row >= NN) continue;
                        float v0 = fmaxf(c[mt][nt][half * 2 + 0] + sh0, 0.f);
                        float v1 = fmaxf(c[mt][nt][half * 2 + 1] + sh1, 0.f);
                        *((__half2*)&g_h[row * 128 + col]) = __floats2half2_rn(v0, v1);
                    }
            }
        } else {
#pragma unroll
            for (int nt = 0; nt < 4; nt++) {
                int col = pass * 64 + wn * 32 + nt * 8 + tg * 2;
                float sh0 = b2[col];
                float sh1 = b2[col + 1];
                float w0 = Wc[col];
                float w1 = Wc[col + 1];
#pragma unroll
                for (int mt = 0; mt < 2; mt++)
#pragma unroll
                    for (int half = 0; half < 2; half++) {
                        float v0 = fmaxf(c[mt][nt][half * 2 + 0] + sh0, 0.f);
                        float v1 = fmaxf(c[mt][nt][half * 2 + 1] + sh1, 0.f);
                        pacc[mt * 2 + half] += v0 * w0 + v1 * w1;
                    }
            }
        }
    }

    if (last) {
        __syncthreads();              // Wp reads done -> reuse as rowdot
        float* rowdot = Xf;
        if (tid < 128) rowdot[tid] = 0.f;
        __syncthreads();
#pragma unroll
        for (int mt = 0; mt < 2; mt++)
#pragma unroll
            for (int half = 0; half < 2; half++) {
                int r = wm * 32 + mt * 16 + gq + half * 8;
                if (row0 + r < NN) atomicAdd(&rowdot[r], pacc[mt * 2 + half]);
            }
        __syncthreads();
        if (tid < 128) {
            int row = row0 + tid;
            if (row < NN) atomicAdd(&out[batch[row]], rowdot[tid]);
        }
    }
}

extern "C" void kernel_launch(void* const* d_in, const int* in_sizes, int n_in,
                              void* d_out, int out_size) {
    const float* x    = (const float*)d_in[0];
    const int* ei     = (const int*)d_in[1];
    const int* batch  = (const int*)d_in[2];
    const float* W1_0 = (const float*)d_in[3];
    const float* b1_0 = (const float*)d_in[4];
    const float* g_0  = (const float*)d_in[5];
    const float* be_0 = (const float*)d_in[6];
    const float* m_0  = (const float*)d_in[7];
    const float* v_0  = (const float*)d_in[8];
    const float* W2_0 = (const float*)d_in[9];
    const float* b2_0 = (const float*)d_in[10];
    const float* W1s  = (const float*)d_in[11];
    const float* b1s  = (const float*)d_in[12];
    const float* gs   = (const float*)d_in[13];
    const float* bes  = (const float*)d_in[14];
    const float* ms   = (const float*)d_in[15];
    const float* vs   = (const float*)d_in[16];
    const float* W2s  = (const float*)d_in[17];
    const float* b2s  = (const float*)d_in[18];
    const float* Wc   = (const float*)d_in[19];
    const float* bc   = (const float*)d_in[20];
    float* out = (float*)d_out;

    cudaFuncSetAttribute(k_fused, cudaFuncAttributeMaxDynamicSharedMemorySize, SMEM_BYTES);

    const int T = 256;
    const int gemm_grid = (NN + 127) / 128;

    // ---- weight pre-pack (+deg zero) + CSR build ----
    k_pack<<<(NN + T - 1) / T, T>>>(W2_0, W1s, W2s);
    k_hist<<<(EE + T - 1) / T, T>>>(ei);
    k_scan1<<<NB_SCAN, 1024>>>();
    k_scan3<<<(NN + T - 1) / T, T>>>();
    k_reorder<<<(EE + T - 1) / T, T>>>(ei);

    // ---- layer 0 (in=3) ----
    k_gather3<<<(NN + T - 1) / T, T>>>(x, bc, out);
    k_fused<<<gemm_grid, 256, SMEM_BYTES>>>(1, 0, 0, 0, W1_0, b1_0, g_0, be_0, m_0, v_0,
                                            b2_0, batch, Wc, out);

    // ---- layers 1..4 ----
    for (int l = 0; l < 4; l++) {
        int last = (l == 3) ? 1 : 0;
        k_gather<<<(NN + 7) / 8, 256>>>();
        k_fused<<<gemm_grid, 256, SMEM_BYTES>>>(0, last, 1 + l, 5 + l,
            W1_0, b1s + l * HH,
            gs + l * HH, bes + l * HH, ms + l * HH, vs + l * HH,
            b2s + l * HH, batch, Wc, out);
    }
}

// round 16
// speedup vs baseline: 1.3099x; 1.3099x over previous
#include <cuda_runtime.h>
#include <cuda_fp16.h>
#include <cstdint>

#define NN 100000
#define EE 600000
#define HH 128
#define GG 1000
#define BN_EPS 1e-5f
#define NB_SCAN 98   // ceil(NN/1024)

// ---- scratch (alloc-free: __device__ globals) ----
__device__ __half g_t[NN * HH];    // h + agg (pre-MLP input), fp16
__device__ __half g_h[NN * HH];    // layer output features, fp16
__device__ float g_t3[NN * 3];     // layer-0 pre-MLP (3 feats)
__device__ uint32_t g_wp[9][64 * 128];  // pre-packed fp16 k-pair weights
// CSR scratch
__device__ int g_deg[NN];
__device__ int g_rowptr[NN + 1];
__device__ int g_cursor[NN];
__device__ int g_bsum[128];
__device__ int g_csr[EE];

// smem layout: Us (fp16 A/activations) + WpA (W1) + WpB (W2)
#define US_HSTRIDE 136                    // halves; conflict-free
#define US_BYTES (128 * US_HSTRIDE * 2)   // 34816
#define WP_WSTRIDE 132                    // words; conflict-free
#define WP_BYTES (64 * WP_WSTRIDE * 4)    // 33792
#define SMEM_BYTES (US_BYTES + 2 * WP_BYTES)  // 102400

__device__ __forceinline__ void cp_async16(uint32_t saddr, const void* gaddr, int szfill) {
    asm volatile("cp.async.ca.shared.global [%0], [%1], 16, %2;"
                 :: "r"(saddr), "l"(gaddr), "r"(szfill) : "memory");
}
__device__ __forceinline__ void cp_commit() {
    asm volatile("cp.async.commit_group;" ::: "memory");
}
template <int N>
__device__ __forceinline__ void cp_wait() {
    asm volatile("cp.async.wait_group %0;" :: "n"(N) : "memory");
}

// ================= weight pre-pack (+ deg zero) =================
__global__ void k_pack(const float* __restrict__ W2_0, const float* __restrict__ W1s,
                       const float* __restrict__ W2s) {
    int idx = blockIdx.x * 256 + threadIdx.x;
    if (idx < NN) g_deg[idx] = 0;
    if (idx >= 9 * 8192) return;
    int m = idx >> 13;
    int w = idx & 8191;
    int kp = w >> 7;
    int col = w & 127;
    const float* W = (m == 0) ? W2_0 : (m <= 4 ? W1s + (m - 1) * 16384 : W2s + (m - 5) * 16384);
    __half2 h = __floats2half2_rn(W[(2 * kp) * 128 + col], W[(2 * kp + 1) * 128 + col]);
    g_wp[m][w] = *(uint32_t*)&h;
}

// ================= CSR build =================
__global__ void k_hist(const int* __restrict__ ei) {
    int e = blockIdx.x * blockDim.x + threadIdx.x;
    if (e < EE) atomicAdd(&g_deg[ei[EE + e]], 1);
}

__global__ __launch_bounds__(1024) void k_scan1() {
    __shared__ int s[1024];
    int tid = threadIdx.x;
    int i = blockIdx.x * 1024 + tid;
    int v = (i < NN) ? g_deg[i] : 0;
    s[tid] = v;
    __syncthreads();
#pragma unroll
    for (int off = 1; off < 1024; off <<= 1) {
        int t = (tid >= off) ? s[tid - off] : 0;
        __syncthreads();
        s[tid] += t;
        __syncthreads();
    }
    if (i < NN) g_rowptr[i] = s[tid] - v;
    if (tid == 1023) g_bsum[blockIdx.x] = s[1023];
}

// merged scan2+scan3: every block redundantly scans the 98 block sums
__global__ void k_scan3() {
    __shared__ int s[128];
    int tid = threadIdx.x;
    if (tid < 128) s[tid] = (tid < NB_SCAN) ? g_bsum[tid] : 0;
    __syncthreads();
#pragma unroll
    for (int off = 1; off < 128; off <<= 1) {
        int t = (tid < 128 && tid >= off) ? s[tid - off] : 0;
        __syncthreads();
        if (tid < 128) s[tid] += t;
        __syncthreads();
    }
    int i = blockIdx.x * blockDim.x + tid;
    if (i < NN) {
        int b = i >> 10;
        int add = (b == 0) ? 0 : s[b - 1];   // exclusive prefix of block sums
        int r = g_rowptr[i] + add;
        g_rowptr[i] = r;
        g_cursor[i] = r;
    }
    if (i == 0) g_rowptr[NN] = EE;
}

__global__ void k_reorder(const int* __restrict__ ei) {
    int e = blockIdx.x * blockDim.x + threadIdx.x;
    if (e >= EE) return;
    int s = ei[e];
    int d = ei[EE + e];
    int pos = atomicAdd(&g_cursor[d], 1);
    g_csr[pos] = s;
}

// ================= gathers =================
__global__ void k_gather3(const float* __restrict__ x, const float* __restrict__ bc,
                          float* __restrict__ out) {
    int n = blockIdx.x * blockDim.x + threadIdx.x;
    if (n < GG) out[n] = bc[0];
    if (n >= NN) return;
    int beg = g_rowptr[n], end = g_rowptr[n + 1];
    float a0 = x[n * 3 + 0], a1 = x[n * 3 + 1], a2 = x[n * 3 + 2];
    for (int p = beg; p < end; p++) {
        int s = g_csr[p];
        a0 += x[s * 3 + 0];
        a1 += x[s * 3 + 1];
        a2 += x[s * 3 + 2];
    }
    g_t3[n * 3 + 0] = a0;
    g_t3[n * 3 + 1] = a1;
    g_t3[n * 3 + 2] = a2;
}

__device__ __forceinline__ void acc_half4(float4& acc, uint2 r) {
    float2 f0 = __half22float2(*(__half2*)&r.x);
    float2 f1 = __half22float2(*(__half2*)&r.y);
    acc.x += f0.x;
    acc.y += f0.y;
    acc.z += f1.x;
    acc.w += f1.y;
}

__global__ __launch_bounds__(256) void k_gather() {
    int n = blockIdx.x * 8 + (threadIdx.x >> 5);
    if (n >= NN) return;
    int lane = threadIdx.x & 31;
    int beg = g_rowptr[n], end = g_rowptr[n + 1];
    float4 acc = make_float4(0.f, 0.f, 0.f, 0.f);
    acc_half4(acc, *((const uint2*)&g_h[n * HH + lane * 4]));
    int p = beg;
    for (; p + 3 < end; p += 4) {
        int s0 = g_csr[p], s1 = g_csr[p + 1], s2 = g_csr[p + 2], s3 = g_csr[p + 3];
        uint2 v0 = *((const uint2*)&g_h[s0 * HH + lane * 4]);
        uint2 v1 = *((const uint2*)&g_h[s1 * HH + lane * 4]);
        uint2 v2 = *((const uint2*)&g_h[s2 * HH + lane * 4]);
        uint2 v3 = *((const uint2*)&g_h[s3 * HH + lane * 4]);
        acc_half4(acc, v0);
        acc_half4(acc, v1);
        acc_half4(acc, v2);
        acc_half4(acc, v3);
    }
    for (; p < end; p++) acc_half4(acc, *((const uint2*)&g_h[g_csr[p] * HH + lane * 4]));
    __half2 o0 = __floats2half2_rn(acc.x, acc.y);
    __half2 o1 = __floats2half2_rn(acc.z, acc.w);
    uint2 o;
    o.x = *(uint32_t*)&o0;
    o.y = *(uint32_t*)&o1;
    *((uint2*)&g_t[n * HH + lane * 4]) = o;
}

// ================= helpers for k_fused =================
__device__ __forceinline__ void stage_weights_async(uint32_t wp_s, const uint32_t* __restrict__ src, int tid) {
#pragma unroll
    for (int i = 0; i < 8; i++) {
        int idx = tid + i * 256;      // uint4 idx 0..2047
        int kp = idx >> 5;
        int c4 = (idx & 31) * 4;
        cp_async16(wp_s + (kp * WP_WSTRIDE + c4) * 4, &src[kp * 128 + c4], 16);
    }
}

__device__ __forceinline__ void ldsm_a(uint32_t a[4], const __half* Us, int rb, int k0, int lane) {
    const __half* p = &Us[(rb + (lane & 15)) * US_HSTRIDE + k0 + ((lane >> 4) << 3)];
    uint32_t addr = (uint32_t)__cvta_generic_to_shared(p);
    asm volatile("ldmatrix.sync.aligned.m8n8.x4.shared.b16 {%0,%1,%2,%3}, [%4];"
                 : "=r"(a[0]), "=r"(a[1]), "=r"(a[2]), "=r"(a[3]) : "r"(addr));
}

// full-K (128) fp16 MMA: acc += Us(rows) @ Wp
__device__ __forceinline__ void mma_fullk(
    float c[2][8][4], const __half* Us, const uint32_t* Wp,
    int wm, int wn, int gq, int tg, int lane) {
#pragma unroll
    for (int ks = 0; ks < 8; ks++) {
        int k0 = ks * 16;
        int kp0 = ks * 8;
        uint32_t a[2][4];
        ldsm_a(a[0], Us, wm * 32, k0, lane);
        ldsm_a(a[1], Us, wm * 32 + 16, k0, lane);
        uint32_t b[8][2];
#pragma unroll
        for (int nt = 0; nt < 8; nt++) {
            int col = wn * 64 + nt * 8 + gq;
            b[nt][0] = Wp[(kp0 + tg) * WP_WSTRIDE + col];
            b[nt][1] = Wp[(kp0 + 4 + tg) * WP_WSTRIDE + col];
        }
#pragma unroll
        for (int mt = 0; mt < 2; mt++)
#pragma unroll
            for (int nt = 0; nt < 8; nt++) {
                asm volatile(
                    "mma.sync.aligned.m16n8k16.row.col.f32.f16.f16.f32 "
                    "{%0,%1,%2,%3}, {%4,%5,%6,%7}, {%8,%9}, {%0,%1,%2,%3};"
                    : "+f"(c[mt][nt][0]), "+f"(c[mt][nt][1]),
                      "+f"(c[mt][nt][2]), "+f"(c[mt][nt][3])
                    : "r"(a[mt][0]), "r"(a[mt][1]), "r"(a[mt][2]), "r"(a[mt][3]),
                      "r"(b[nt][0]), "r"(b[nt][1]));
            }
    }
}

// ================= fused per-layer MLP (cp.async triple-buffer) =================
__global__ __launch_bounds__(256, 2) void k_fused(
    int layer0, int last, int m1, int m2,
    const float* __restrict__ W1_0, const float* __restrict__ b1,
    const float* __restrict__ gam, const float* __restrict__ bet,
    const float* __restrict__ mu, const float* __restrict__ var,
    const float* __restrict__ b2,
    const int* __restrict__ batch, const float* __restrict__ Wc,
    float* __restrict__ out) {
    extern __shared__ char smem[];
    __half* Us = (__half*)smem;
    uint32_t* WpA = (uint32_t*)(smem + US_BYTES);
    uint32_t* WpB = (uint32_t*)(smem + US_BYTES + WP_BYTES);
    float* Xf = (float*)(smem + US_BYTES);   // alias WpA: layer0 params / rowdot
    uint32_t us_s = (uint32_t)__cvta_generic_to_shared(Us);
    uint32_t wpa_s = (uint32_t)__cvta_generic_to_shared(WpA);
    uint32_t wpb_s = (uint32_t)__cvta_generic_to_shared(WpB);

    int tid = threadIdx.x;
    int warp = tid >> 5, lane = tid & 31;
    int wm = warp & 3;
    int wn = warp >> 2;
    int gq = lane >> 2;
    int tg = lane & 3;
    int row0 = blockIdx.x * 128;

    // ================= stage 1 =================
    if (layer0) {
        // prefetch W2 (group0) while doing the ALU mini-MLP
        stage_weights_async(wpb_s, g_wp[m2], tid);
        cp_commit();

        float* W1s = Xf;          // 384
        float* sc = Xf + 384;     // 128
        float* sh = Xf + 512;     // 128
        float* t3s = Xf + 640;    // 384
        for (int i = tid; i < 384; i += 256) {
            W1s[i] = W1_0[i];
            int gi = row0 * 3 + i;
            t3s[i] = (gi < NN * 3) ? g_t3[gi] : 0.f;
        }
        if (tid < 128) {
            float s = gam[tid] * rsqrtf(var[tid] + BN_EPS);
            sc[tid] = s;
            sh[tid] = bet[tid] + (b1[tid] - mu[tid]) * s;
        }
        __syncthreads();
#pragma unroll 4
        for (int i = 0; i < 64; i++) {
            int idx = tid + i * 256;
            int r = idx >> 7, c = idx & 127;
            float x0 = t3s[r * 3 + 0];
            float x1 = t3s[r * 3 + 1];
            float x2 = t3s[r * 3 + 2];
            float u = x0 * W1s[c] + x1 * W1s[128 + c] + x2 * W1s[256 + c];
            u = fmaxf(u * sc[c] + sh[c], 0.f);
            Us[r * US_HSTRIDE + c] = __float2half(u);
        }
        cp_wait<0>();
        __syncthreads();
    } else {
        // group0: A tile + W1; group1: W2
#pragma unroll
        for (int i = 0; i < 8; i++) {
            int idx = tid + i * 256;   // 2048 × 16B
            int r = idx >> 4;
            int q = idx & 15;
            int row = row0 + r;
            cp_async16(us_s + (r * US_HSTRIDE + q * 8) * 2,
                       &g_t[row * 128 + q * 8], (row < NN) ? 16 : 0);
        }
        stage_weights_async(wpa_s, g_wp[m1], tid);
        cp_commit();
        stage_weights_async(wpb_s, g_wp[m2], tid);
        cp_commit();

        cp_wait<1>();   // A + W1 ready; W2 still in flight
        __syncthreads();

        float c1[2][8][4];
#pragma unroll
        for (int mt = 0; mt < 2; mt++)
#pragma unroll
            for (int nt = 0; nt < 8; nt++)
#pragma unroll
                for (int r = 0; r < 4; r++) c1[mt][nt][r] = 0.f;

        mma_fullk(c1, Us, WpA, wm, wn, gq, tg, lane);
        cp_wait<0>();      // W2 arrived (overlapped with MMA)
        __syncthreads();   // Us reads done before overwrite; W2 visible after

        // BN + ReLU -> Us in place (fp16)
#pragma unroll
        for (int nt = 0; nt < 8; nt++) {
            int col = wn * 64 + nt * 8 + tg * 2;
            float s0 = gam[col] * rsqrtf(var[col] + BN_EPS);
            float s1 = gam[col + 1] * rsqrtf(var[col + 1] + BN_EPS);
            float sh0 = bet[col] + (b1[col] - mu[col]) * s0;
            float sh1 = bet[col + 1] + (b1[col + 1] - mu[col + 1]) * s1;
#pragma unroll
            for (int mt = 0; mt < 2; mt++) {
                int rb = wm * 32 + mt * 16 + gq;
#pragma unroll
                for (int half = 0; half < 2; half++) {
                    int r = rb + half * 8;
                    float v0 = fmaxf(c1[mt][nt][half * 2 + 0] * s0 + sh0, 0.f);
                    float v1 = fmaxf(c1[mt][nt][half * 2 + 1] * s1 + sh1, 0.f);
                    *((__half2*)&Us[r * US_HSTRIDE + col]) = __floats2half2_rn(v0, v1);
                }
            }
        }
        __syncthreads();
    }

    // ================= stage 2: h = ReLU(Us @ W2 + b2) =================
    float c2[2][8][4];
#pragma unroll
    for (int mt = 0; mt < 2; mt++)
#pragma unroll
        for (int nt = 0; nt < 8; nt++)
#pragma unroll
            for (int r = 0; r < 4; r++) c2[mt][nt][r] = 0.f;

    mma_fullk(c2, Us, WpB, wm, wn, gq, tg, lane);

    if (!last) {
        // epilogue: bias + ReLU -> g_h (fp16)
#pragma unroll
        for (int nt = 0; nt < 8; nt++) {
            int col = wn * 64 + nt * 8 + tg * 2;
            float sh0 = b2[col];
            float sh1 = b2[col + 1];
#pragma unroll
            for (int mt = 0; mt < 2; mt++) {
                int r0 = row0 + wm * 32 + mt * 16 + gq;
#pragma unroll
                for (int half = 0; half < 2; half++) {
                    int row = r0 + half * 8;
                    if (row >= NN) continue;
                    float v0 = fmaxf(c2[mt][nt][half * 2 + 0] + sh0, 0.f);
                    float v1 = fmaxf(c2[mt][nt][half * 2 + 1] + sh1, 0.f);
                    *((__half2*)&g_h[row * 128 + col]) = __floats2half2_rn(v0, v1);
                }
            }
        }
    } else {
        // fused pool+classify; rowdot aliases WpA -> sync before reuse
        __syncthreads();
        float* rowdot = Xf;
        if (tid < 128) rowdot[tid] = 0.f;
        __syncthreads();
#pragma unroll
        for (int mt = 0; mt < 2; mt++) {
#pragma unroll
            for (int half = 0; half < 2; half++) {
                int r = wm * 32 + mt * 16 + gq + half * 8;
                if (row0 + r >= NN) continue;
                float p = 0.f;
#pragma unroll
                for (int nt = 0; nt < 8; nt++) {
                    int col = wn * 64 + nt * 8 + tg * 2;
                    float v0 = fmaxf(c2[mt][nt][half * 2 + 0] + b2[col], 0.f);
                    float v1 = fmaxf(c2[mt][nt][half * 2 + 1] + b2[col + 1], 0.f);
                    p += v0 * Wc[col] + v1 * Wc[col + 1];
                }
                atomicAdd(&rowdot[r], p);
            }
        }
        __syncthreads();
        if (tid < 128) {
            int row = row0 + tid;
            if (row < NN) atomicAdd(&out[batch[row]], rowdot[tid]);
        }
    }
}

extern "C" void kernel_launch(void* const* d_in, const int* in_sizes, int n_in,
                              void* d_out, int out_size) {
    const float* x    = (const float*)d_in[0];
    const int* ei     = (const int*)d_in[1];
    const int* batch  = (const int*)d_in[2];
    const float* W1_0 = (const float*)d_in[3];
    const float* b1_0 = (const float*)d_in[4];
    const float* g_0  = (const float*)d_in[5];
    const float* be_0 = (const float*)d_in[6];
    const float* m_0  = (const float*)d_in[7];
    const float* v_0  = (const float*)d_in[8];
    const float* W2_0 = (const float*)d_in[9];
    const float* b2_0 = (const float*)d_in[10];
    const float* W1s  = (const float*)d_in[11];
    const float* b1s  = (const float*)d_in[12];
    const float* gs   = (const float*)d_in[13];
    const float* bes  = (const float*)d_in[14];
    const float* ms   = (const float*)d_in[15];
    const float* vs   = (const float*)d_in[16];
    const float* W2s  = (const float*)d_in[17];
    const float* b2s  = (const float*)d_in[18];
    const float* Wc   = (const float*)d_in[19];
    const float* bc   = (const float*)d_in[20];
    float* out = (float*)d_out;

    cudaFuncSetAttribute(k_fused, cudaFuncAttributeMaxDynamicSharedMemorySize, SMEM_BYTES);

    const int T = 256;
    const int gemm_grid = (NN + 127) / 128;

    // ---- weight pre-pack (+deg zero) + CSR build ----
    k_pack<<<(NN + T - 1) / T, T>>>(W2_0, W1s, W2s);
    k_hist<<<(EE + T - 1) / T, T>>>(ei);
    k_scan1<<<NB_SCAN, 1024>>>();
    k_scan3<<<(NN + T - 1) / T, T>>>();
    k_reorder<<<(EE + T - 1) / T, T>>>(ei);

    // ---- layer 0 (in=3) ----
    k_gather3<<<(NN + T - 1) / T, T>>>(x, bc, out);
    k_fused<<<gemm_grid, 256, SMEM_BYTES>>>(1, 0, 0, 0, W1_0, b1_0, g_0, be_0, m_0, v_0,
                                            b2_0, batch, Wc, out);

    // ---- layers 1..4 ----
    for (int l = 0; l < 4; l++) {
        int last = (l == 3) ? 1 : 0;
        k_gather<<<(NN + 7) / 8, 256>>>();
        k_fused<<<gemm_grid, 256, SMEM_BYTES>>>(0, last, 1 + l, 5 + l,
            W1_0, b1s + l * HH,
            gs + l * HH, bes + l * HH, ms + l * HH, vs + l * HH,
            b2s + l * HH, batch, Wc, out);
    }
}